// round 1
// baseline (speedup 1.0000x reference)
#include <cuda_runtime.h>

// Problem constants
#define BB   16
#define NN   2048
#define TT   168
#define DD   64
#define MM   2216          // N + T  (MM % 8 == 0)
#define TILE 128
#define NT   18            // ceil(2216/128)
#define PAIRS 171          // NT*(NT+1)/2
#define PITCH 132          // 128 + 4 pad floats: conflict-free f4 compute reads
#define SMEM_FLOATS (2*64*PITCH)   // As + Bs = 16896 floats = 67584 B (Cs reuses all of it)
#define SMEM_BYTES  (SMEM_FLOATS*4)

__device__ __forceinline__ float tanh_relu(float x) {
    x = fmaxf(x, 0.0f);
    float y;
    asm("tanh.approx.f32 %0, %1;" : "=f"(y) : "f"(x));
    return y;
}

__global__ __launch_bounds__(256, 2)
void stg_kernel(const float* __restrict__ sp, const float* __restrict__ tp,
                float* __restrict__ out)
{
    extern __shared__ float sm[];
    float* As = sm;                 // [64][PITCH], k-major: As[k*PITCH + row]
    float* Bs = sm + 64 * PITCH;

    const int b = blockIdx.y;
    int p = blockIdx.x;
    int ti = 0;
    while (p >= NT - ti) { p -= NT - ti; ++ti; }
    const int tj = ti + p;          // ti <= tj

    const int t = threadIdx.x;
    const int rowA0 = ti * TILE;
    const int rowB0 = tj * TILE;

    // ---- load both 128x64 tiles into k-major SMEM (coalesced global reads) ----
    // idx over 8192 floats per tile: k = idx&63 (fastest, matches row-major global), row = idx>>6
    #pragma unroll
    for (int i = 0; i < 32; ++i) {
        int idx = i * 256 + t;
        int k   = idx & 63;
        int row = idx >> 6;
        float va = 0.0f, vb = 0.0f;
        int gra = rowA0 + row;
        if (gra < MM) {
            const float* pa = (gra < NN) ? sp + ((size_t)b * NN + gra) * DD
                                         : tp + ((size_t)b * TT + (gra - NN)) * DD;
            va = pa[k];
        }
        int grb = rowB0 + row;
        if (grb < MM) {
            const float* pb = (grb < NN) ? sp + ((size_t)b * NN + grb) * DD
                                         : tp + ((size_t)b * TT + (grb - NN)) * DD;
            vb = pb[k];
        }
        As[k * PITCH + row] = va;
        Bs[k * PITCH + row] = vb;
    }
    __syncthreads();

    const int tx = t & 15, ty = t >> 4;   // 16x16 threads, 8x8 microtile each
    float acc[8][8];
    #pragma unroll
    for (int i = 0; i < 8; ++i)
        #pragma unroll
        for (int j = 0; j < 8; ++j) acc[i][j] = 0.0f;

    #pragma unroll 8
    for (int k = 0; k < 64; ++k) {
        float4 a0 = *(const float4*)&As[k * PITCH + ty * 8];
        float4 a1 = *(const float4*)&As[k * PITCH + ty * 8 + 4];
        float4 b0 = *(const float4*)&Bs[k * PITCH + tx * 8];
        float4 b1 = *(const float4*)&Bs[k * PITCH + tx * 8 + 4];
        float av[8] = {a0.x, a0.y, a0.z, a0.w, a1.x, a1.y, a1.z, a1.w};
        float bv[8] = {b0.x, b0.y, b0.z, b0.w, b1.x, b1.y, b1.z, b1.w};
        #pragma unroll
        for (int i = 0; i < 8; ++i)
            #pragma unroll
            for (int j = 0; j < 8; ++j)
                acc[i][j] = fmaf(av[i], bv[j], acc[i][j]);
    }

    // activation
    #pragma unroll
    for (int i = 0; i < 8; ++i)
        #pragma unroll
        for (int j = 0; j < 8; ++j)
            acc[i][j] = tanh_relu(acc[i][j]);

    // ---- direct write: block rows in ti-tile, cols in tj-tile (coalesced f4) ----
    {
        const int gc = rowB0 + tx * 8;         // multiple of 8; MM%8==0 -> whole 8-wide strip valid iff gc<MM
        #pragma unroll
        for (int i = 0; i < 8; ++i) {
            int gr = rowA0 + ty * 8 + i;
            if (gr < MM && gc < MM) {
                size_t base = ((size_t)b * MM + gr) * MM + gc;
                *(float4*)&out[base]     = make_float4(acc[i][0], acc[i][1], acc[i][2], acc[i][3]);
                *(float4*)&out[base + 4] = make_float4(acc[i][4], acc[i][5], acc[i][6], acc[i][7]);
            }
        }
    }

    // ---- mirror write via swizzled SMEM transpose (skip on diagonal tiles) ----
    if (ti != tj) {
        __syncthreads();                       // everyone done reading As/Bs
        float* Cs = sm;                        // logical [lc=128][lr=128], f4-granular XOR swizzle
        // store: thread owns lr = 8*ty + ii, lc = 8*tx + jj; 4 consecutive lr share one f4
        #pragma unroll
        for (int j = 0; j < 8; ++j) {
            int lc = tx * 8 + j;
            int f  = (lc ^ (lc >> 3)) & 7;
            float* base = &Cs[lc * PITCH];
            int s0 = (2 * ty)     ^ f;         // (lr>>2) for ii 0..3
            int s1 = (2 * ty + 1) ^ f;         // (lr>>2) for ii 4..7
            *(float4*)&base[4 * s0] = make_float4(acc[0][j], acc[1][j], acc[2][j], acc[3][j]);
            *(float4*)&base[4 * s1] = make_float4(acc[4][j], acc[5][j], acc[6][j], acc[7][j]);
        }
        __syncthreads();
        // read back rows of the transpose, write out[b][gc][gr] coalesced along gr
        #pragma unroll
        for (int i = 0; i < 16; ++i) {
            int u   = i * 256 + t;             // f4 index, 4096 total
            int lr4 = u & 31;
            int lc  = u >> 5;
            int f   = (lc ^ (lc >> 3)) & 7;
            float4 v = *(const float4*)&Cs[lc * PITCH + 4 * (lr4 ^ f)];
            int gc = rowB0 + lc;               // output row (in tj-tile)
            int gr = rowA0 + lr4 * 4;          // output col group (in ti-tile); MM%4==0
            if (gc < MM && gr < MM) {
                *(float4*)&out[((size_t)b * MM + gc) * MM + gr] = v;
            }
        }
    }
}

extern "C" void kernel_launch(void* const* d_in, const int* in_sizes, int n_in,
                              void* d_out, int out_size)
{
    const float* sp = (const float*)d_in[0];   // spatial  [16,2048,64] f32
    const float* tp = (const float*)d_in[1];   // temporal [16, 168,64] f32
    float* out = (float*)d_out;                // [16,2216,2216] f32

    cudaFuncSetAttribute(stg_kernel, cudaFuncAttributeMaxDynamicSharedMemorySize, SMEM_BYTES);
    dim3 grid(PAIRS, BB);
    stg_kernel<<<grid, 256, SMEM_BYTES>>>(sp, tp, out);
}

// round 3
// speedup vs baseline: 1.3425x; 1.3425x over previous
#include <cuda_runtime.h>
#include <cuda_bf16.h>
#include <cstdint>

// Problem constants
#define BB   16
#define NN   2048
#define TT   168
#define DD   64
#define MM   2216            // N + T, even
#define TM   128
#define TN   128
#define NTI  18              // ceil(MM/128)
#define NTJ  18

// SMEM regions (bf16 [128][64] tiles, 128B rows, SW128-swizzled), 16KB each
#define AHI_OFF 0
#define ALO_OFF 16384
#define BHI_OFF 32768
#define BLO_OFF 49152
#define SMEM_BYTES 65536

__device__ __forceinline__ uint32_t smem_u32(const void* p) {
    uint32_t a;
    asm("{ .reg .u64 t; cvta.to.shared.u64 t, %1; cvt.u32.u64 %0, t; }" : "=r"(a) : "l"(p));
    return a;
}

__device__ __forceinline__ float tanh_relu(float x) {
    x = fmaxf(x, 0.0f);
    float y;
    asm("tanh.approx.f32 %0, %1;" : "=f"(y) : "f"(x));
    return y;
}

__device__ __forceinline__ uint32_t sw128(uint32_t off) {
    return off ^ ((off >> 3) & 0x70);
}

// convert float4 -> hi/lo bf16x2 pairs, store 8B each into swizzled smem regions
__device__ __forceinline__ void split_store(char* hi_base, char* lo_base,
                                            int row, int c4, float4 v) {
    uint32_t off = row * 128 + c4 * 8;
    uint32_t sw  = sw128(off);
    __nv_bfloat162 h01 = __floats2bfloat162_rn(v.x, v.y);
    __nv_bfloat162 h23 = __floats2bfloat162_rn(v.z, v.w);
    float lx = v.x - __bfloat162float(__low2bfloat16(h01));
    float ly = v.y - __bfloat162float(__high2bfloat16(h01));
    float lz = v.z - __bfloat162float(__low2bfloat16(h23));
    float lw = v.w - __bfloat162float(__high2bfloat16(h23));
    __nv_bfloat162 l01 = __floats2bfloat162_rn(lx, ly);
    __nv_bfloat162 l23 = __floats2bfloat162_rn(lz, lw);
    uint2 hp, lp;
    hp.x = *(uint32_t*)&h01; hp.y = *(uint32_t*)&h23;
    lp.x = *(uint32_t*)&l01; lp.y = *(uint32_t*)&l23;
    *(uint2*)(hi_base + sw) = hp;
    *(uint2*)(lo_base + sw) = lp;
}

__device__ __forceinline__ void ldsm_x4(uint32_t addr, uint32_t& r0, uint32_t& r1,
                                        uint32_t& r2, uint32_t& r3) {
    asm volatile("ldmatrix.sync.aligned.m8n8.x4.shared.b16 {%0,%1,%2,%3}, [%4];"
                 : "=r"(r0), "=r"(r1), "=r"(r2), "=r"(r3) : "r"(addr));
}

__device__ __forceinline__ void mma16816(float* c, const uint32_t* a, const uint32_t* b) {
    asm volatile(
        "mma.sync.aligned.m16n8k16.row.col.f32.bf16.bf16.f32 "
        "{%0,%1,%2,%3}, {%4,%5,%6,%7}, {%8,%9}, {%0,%1,%2,%3};"
        : "+f"(c[0]), "+f"(c[1]), "+f"(c[2]), "+f"(c[3])
        : "r"(a[0]), "r"(a[1]), "r"(a[2]), "r"(a[3]), "r"(b[0]), "r"(b[1]));
}

__global__ __launch_bounds__(256, 2)
void stg_hmma_kernel(const float* __restrict__ sp, const float* __restrict__ tp,
                     float* __restrict__ out)
{
    extern __shared__ char smem[];
    const uint32_t smem_base = smem_u32(smem);

    const int t    = threadIdx.x;
    const int lane = t & 31;
    const int wid  = t >> 5;

    const int b    = blockIdx.y;
    const int ti   = blockIdx.x % NTI;
    const int tj   = blockIdx.x / NTI;
    const int row0 = ti * TM;
    const int col0 = tj * TN;

    // ---- load + split-convert A (rows row0..) and B (rows col0..) tiles ----
    #pragma unroll
    for (int i = 0; i < 8; ++i) {
        int idx = i * 256 + t;
        int r   = idx >> 4;
        int c4  = idx & 15;
        int g   = row0 + r;
        float4 v = make_float4(0.f, 0.f, 0.f, 0.f);
        if (g < MM) {
            const float* p = (g < NN) ? sp + ((size_t)b * NN + g) * DD
                                      : tp + ((size_t)b * TT + (g - NN)) * DD;
            v = ((const float4*)p)[c4];
        }
        split_store(smem + AHI_OFF, smem + ALO_OFF, r, c4, v);
    }
    #pragma unroll
    for (int i = 0; i < 8; ++i) {
        int idx = i * 256 + t;
        int r   = idx >> 4;
        int c4  = idx & 15;
        int g   = col0 + r;
        float4 v = make_float4(0.f, 0.f, 0.f, 0.f);
        if (g < MM) {
            const float* p = (g < NN) ? sp + ((size_t)b * NN + g) * DD
                                      : tp + ((size_t)b * TT + (g - NN)) * DD;
            v = ((const float4*)p)[c4];
        }
        split_store(smem + BHI_OFF, smem + BLO_OFF, r, c4, v);
    }
    __syncthreads();

    // ---- warp tiles: 4 (m) x 2 (n) warps, each 32x64 ----
    const int m0w = (wid & 3) * 32;
    const int n0w = (wid >> 2) * 64;

    float acc[2][8][4];
    #pragma unroll
    for (int mi = 0; mi < 2; ++mi)
        #pragma unroll
        for (int ni = 0; ni < 8; ++ni)
            #pragma unroll
            for (int q = 0; q < 4; ++q) acc[mi][ni][q] = 0.0f;

    // precompute per-lane ldmatrix base offsets (k0=0), advance by 16B per 8 k
    // A: row = m0w + mi*16 + (lane&15), chunk = lane>>4
    // B: row = n0w + bi*16 + ((lane>>4)<<3) + (lane&7), chunk = (lane>>3)&1
    const int a_row = m0w + (lane & 15);
    const int a_chk = lane >> 4;
    const int b_rowb = n0w + ((lane >> 4) << 3) + (lane & 7);
    const int b_chk = (lane >> 3) & 1;

    #pragma unroll
    for (int pass = 0; pass < 3; ++pass) {
        const uint32_t abase = smem_base + (pass == 2 ? ALO_OFF : AHI_OFF);
        const uint32_t bbase = smem_base + (pass == 1 ? BLO_OFF : BHI_OFF);
        #pragma unroll
        for (int kk = 0; kk < 4; ++kk) {
            const int kc = kk * 2;   // k-chunk (8 bf16 = 16B units)
            uint32_t af[2][4];
            #pragma unroll
            for (int mi = 0; mi < 2; ++mi) {
                uint32_t off = (uint32_t)(a_row + mi * 16) * 128 + (uint32_t)(kc + a_chk) * 16;
                ldsm_x4(abase + sw128(off), af[mi][0], af[mi][1], af[mi][2], af[mi][3]);
            }
            uint32_t bf[8][2];
            #pragma unroll
            for (int bi = 0; bi < 4; ++bi) {
                uint32_t off = (uint32_t)(b_rowb + bi * 16) * 128 + (uint32_t)(kc + b_chk) * 16;
                ldsm_x4(bbase + sw128(off), bf[2*bi][0], bf[2*bi][1], bf[2*bi+1][0], bf[2*bi+1][1]);
            }
            #pragma unroll
            for (int mi = 0; mi < 2; ++mi)
                #pragma unroll
                for (int ni = 0; ni < 8; ++ni)
                    mma16816(acc[mi][ni], af[mi], bf[ni]);
        }
    }

    // ---- epilogue: tanh(relu(.)) + float2 stores ----
    #pragma unroll
    for (int mi = 0; mi < 2; ++mi) {
        #pragma unroll
        for (int rh = 0; rh < 2; ++rh) {
            const int gr = row0 + m0w + mi * 16 + rh * 8 + (lane >> 2);
            if (gr >= MM) continue;
            const size_t rbase = ((size_t)b * MM + gr) * MM;
            #pragma unroll
            for (int ni = 0; ni < 8; ++ni) {
                const int gc = col0 + n0w + ni * 8 + (lane & 3) * 2;
                if (gc < MM) {
                    float2 v;
                    v.x = tanh_relu(acc[mi][ni][rh * 2]);
                    v.y = tanh_relu(acc[mi][ni][rh * 2 + 1]);
                    *(float2*)&out[rbase + gc] = v;
                }
            }
        }
    }
}

extern "C" void kernel_launch(void* const* d_in, const int* in_sizes, int n_in,
                              void* d_out, int out_size)
{
    const float* sp = (const float*)d_in[0];   // spatial  [16,2048,64] f32
    const float* tp = (const float*)d_in[1];   // temporal [16, 168,64] f32
    float* out = (float*)d_out;                // [16,2216,2216] f32

    cudaFuncSetAttribute(stg_hmma_kernel, cudaFuncAttributeMaxDynamicSharedMemorySize, SMEM_BYTES);
    dim3 grid(NTI * NTJ, BB);
    stg_hmma_kernel<<<grid, 256, SMEM_BYTES>>>(sp, tp, out);
}

// round 4
// speedup vs baseline: 1.8232x; 1.3581x over previous
#include <cuda_runtime.h>
#include <cuda_bf16.h>
#include <cstdint>

// Problem constants
#define BB   16
#define NN   2048
#define TT   168
#define DD   64
#define MM   2216            // N + T
#define TM   128
#define NT   18              // ceil(MM/128)
#define PAIRS 171            // NT*(NT+1)/2

// SMEM regions (bf16 [128][64] tiles, 128B rows, SW128-swizzled), 16KB each.
// After MMA, whole region is reused as Cs: float [128 cols][pitch 132].
#define AHI_OFF 0
#define ALO_OFF 16384
#define BHI_OFF 32768
#define BLO_OFF 49152
#define CS_PITCH 132
#define SMEM_BYTES (128*CS_PITCH*4)   // 67584 >= 65536

__device__ __forceinline__ uint32_t smem_u32(const void* p) {
    uint32_t a;
    asm("{ .reg .u64 t; cvta.to.shared.u64 t, %1; cvt.u32.u64 %0, t; }" : "=r"(a) : "l"(p));
    return a;
}

__device__ __forceinline__ float tanh_relu(float x) {
    x = fmaxf(x, 0.0f);
    float y;
    asm("tanh.approx.f32 %0, %1;" : "=f"(y) : "f"(x));
    return y;
}

__device__ __forceinline__ uint32_t sw128(uint32_t off) {
    return off ^ ((off >> 3) & 0x70);
}

__device__ __forceinline__ void split_store(char* hi_base, char* lo_base,
                                            int row, int c4, float4 v) {
    uint32_t off = row * 128 + c4 * 8;
    uint32_t sw  = sw128(off);
    __nv_bfloat162 h01 = __floats2bfloat162_rn(v.x, v.y);
    __nv_bfloat162 h23 = __floats2bfloat162_rn(v.z, v.w);
    float lx = v.x - __bfloat162float(__low2bfloat16(h01));
    float ly = v.y - __bfloat162float(__high2bfloat16(h01));
    float lz = v.z - __bfloat162float(__low2bfloat16(h23));
    float lw = v.w - __bfloat162float(__high2bfloat16(h23));
    __nv_bfloat162 l01 = __floats2bfloat162_rn(lx, ly);
    __nv_bfloat162 l23 = __floats2bfloat162_rn(lz, lw);
    uint2 hp, lp;
    hp.x = *(uint32_t*)&h01; hp.y = *(uint32_t*)&h23;
    lp.x = *(uint32_t*)&l01; lp.y = *(uint32_t*)&l23;
    *(uint2*)(hi_base + sw) = hp;
    *(uint2*)(lo_base + sw) = lp;
}

__device__ __forceinline__ void ldsm_x4(uint32_t addr, uint32_t& r0, uint32_t& r1,
                                        uint32_t& r2, uint32_t& r3) {
    asm volatile("ldmatrix.sync.aligned.m8n8.x4.shared.b16 {%0,%1,%2,%3}, [%4];"
                 : "=r"(r0), "=r"(r1), "=r"(r2), "=r"(r3) : "r"(addr));
}

__device__ __forceinline__ void mma16816(float* c, const uint32_t* a, const uint32_t* b) {
    asm volatile(
        "mma.sync.aligned.m16n8k16.row.col.f32.bf16.bf16.f32 "
        "{%0,%1,%2,%3}, {%4,%5,%6,%7}, {%8,%9}, {%0,%1,%2,%3};"
        : "+f"(c[0]), "+f"(c[1]), "+f"(c[2]), "+f"(c[3])
        : "r"(a[0]), "r"(a[1]), "r"(a[2]), "r"(a[3]), "r"(b[0]), "r"(b[1]));
}

__global__ __launch_bounds__(256, 2)
void stg_sym_kernel(const float* __restrict__ sp, const float* __restrict__ tp,
                    float* __restrict__ out)
{
    extern __shared__ char smem[];
    const uint32_t smem_base = smem_u32(smem);

    const int t    = threadIdx.x;
    const int lane = t & 31;
    const int wid  = t >> 5;

    const int b = blockIdx.y;
    int p = blockIdx.x;
    int ti = 0;
    while (p >= NT - ti) { p -= NT - ti; ++ti; }
    const int tj = ti + p;                 // ti <= tj
    const int row0 = ti * TM;
    const int col0 = tj * TM;
    const bool diag = (ti == tj);

    // ---- load + split-convert A tile (rows row0..) and, if off-diag, B tile ----
    #pragma unroll
    for (int i = 0; i < 8; ++i) {
        int idx = i * 256 + t;
        int r   = idx >> 4;
        int c4  = idx & 15;
        int g   = row0 + r;
        float4 v = make_float4(0.f, 0.f, 0.f, 0.f);
        if (g < MM) {
            const float* ptr = (g < NN) ? sp + ((size_t)b * NN + g) * DD
                                        : tp + ((size_t)b * TT + (g - NN)) * DD;
            v = ((const float4*)ptr)[c4];
        }
        split_store(smem + AHI_OFF, smem + ALO_OFF, r, c4, v);
    }
    if (!diag) {
        #pragma unroll
        for (int i = 0; i < 8; ++i) {
            int idx = i * 256 + t;
            int r   = idx >> 4;
            int c4  = idx & 15;
            int g   = col0 + r;
            float4 v = make_float4(0.f, 0.f, 0.f, 0.f);
            if (g < MM) {
                const float* ptr = (g < NN) ? sp + ((size_t)b * NN + g) * DD
                                            : tp + ((size_t)b * TT + (g - NN)) * DD;
                v = ((const float4*)ptr)[c4];
            }
            split_store(smem + BHI_OFF, smem + BLO_OFF, r, c4, v);
        }
    }
    __syncthreads();

    // ---- warp tiles: 4 (m) x 2 (n) warps, each 32x64 ----
    const int m0w = (wid & 3) * 32;
    const int n0w = (wid >> 2) * 64;

    float acc[2][8][4];
    #pragma unroll
    for (int mi = 0; mi < 2; ++mi)
        #pragma unroll
        for (int ni = 0; ni < 8; ++ni)
            #pragma unroll
            for (int q = 0; q < 4; ++q) acc[mi][ni][q] = 0.0f;

    const int a_row  = m0w + (lane & 15);
    const int a_chk  = lane >> 4;
    const int b_rowb = n0w + ((lane >> 4) << 3) + (lane & 7);
    const int b_chk  = (lane >> 3) & 1;

    const uint32_t BHI = diag ? AHI_OFF : BHI_OFF;
    const uint32_t BLO = diag ? ALO_OFF : BLO_OFF;

    #pragma unroll
    for (int pass = 0; pass < 3; ++pass) {
        const uint32_t abase = smem_base + (pass == 2 ? ALO_OFF : AHI_OFF);
        const uint32_t bbase = smem_base + (pass == 1 ? BLO : BHI);
        #pragma unroll
        for (int kk = 0; kk < 4; ++kk) {
            const int kc = kk * 2;
            uint32_t af[2][4];
            #pragma unroll
            for (int mi = 0; mi < 2; ++mi) {
                uint32_t off = (uint32_t)(a_row + mi * 16) * 128 + (uint32_t)(kc + a_chk) * 16;
                ldsm_x4(abase + sw128(off), af[mi][0], af[mi][1], af[mi][2], af[mi][3]);
            }
            uint32_t bf[8][2];
            #pragma unroll
            for (int bi = 0; bi < 4; ++bi) {
                uint32_t off = (uint32_t)(b_rowb + bi * 16) * 128 + (uint32_t)(kc + b_chk) * 16;
                ldsm_x4(bbase + sw128(off), bf[2*bi][0], bf[2*bi][1], bf[2*bi+1][0], bf[2*bi+1][1]);
            }
            #pragma unroll
            for (int mi = 0; mi < 2; ++mi)
                #pragma unroll
                for (int ni = 0; ni < 8; ++ni)
                    mma16816(acc[mi][ni], af[mi], bf[ni]);
        }
    }

    // ---- activation in place ----
    #pragma unroll
    for (int mi = 0; mi < 2; ++mi)
        #pragma unroll
        for (int ni = 0; ni < 8; ++ni)
            #pragma unroll
            for (int q = 0; q < 4; ++q)
                acc[mi][ni][q] = tanh_relu(acc[mi][ni][q]);

    // ---- direct write: out[row0+r][col0+c], coalesced float2 ----
    #pragma unroll
    for (int mi = 0; mi < 2; ++mi) {
        #pragma unroll
        for (int rh = 0; rh < 2; ++rh) {
            const int gr = row0 + m0w + mi * 16 + rh * 8 + (lane >> 2);
            if (gr >= MM) continue;
            const size_t rbase = ((size_t)b * MM + gr) * MM;
            #pragma unroll
            for (int ni = 0; ni < 8; ++ni) {
                const int gc = col0 + n0w + ni * 8 + (lane & 3) * 2;
                if (gc < MM) {
                    float2 v;
                    v.x = acc[mi][ni][rh * 2];
                    v.y = acc[mi][ni][rh * 2 + 1];
                    *(float2*)&out[rbase + gc] = v;
                }
            }
        }
    }

    // ---- mirror write via SMEM transpose (off-diagonal only) ----
    if (!diag) {
        __syncthreads();                   // done reading A/B tiles
        float* Cs = (float*)smem;          // [c:128][r: pitch 132]
        #pragma unroll
        for (int mi = 0; mi < 2; ++mi) {
            #pragma unroll
            for (int rh = 0; rh < 2; ++rh) {
                const int r = m0w + mi * 16 + rh * 8 + (lane >> 2);
                #pragma unroll
                for (int ni = 0; ni < 8; ++ni) {
                    const int c = n0w + ni * 8 + (lane & 3) * 2;
                    Cs[(c)     * CS_PITCH + r] = acc[mi][ni][rh * 2];
                    Cs[(c + 1) * CS_PITCH + r] = acc[mi][ni][rh * 2 + 1];
                }
            }
        }
        __syncthreads();
        // read rows of Cs (f4, conflict-free), write out[col0+c][row0+r] coalesced
        #pragma unroll
        for (int i = 0; i < 16; ++i) {
            int u   = i * 256 + t;         // 4096 f4 total
            int lr4 = u & 31;
            int lc  = u >> 5;
            float4 v = *(const float4*)&Cs[lc * CS_PITCH + 4 * lr4];
            int gr_out = col0 + lc;        // output row (in tj tile)
            int gc_out = row0 + 4 * lr4;   // output cols (in ti tile), MM%4==0
            if (gr_out < MM && gc_out < MM) {
                *(float4*)&out[((size_t)b * MM + gr_out) * MM + gc_out] = v;
            }
        }
    }
}

extern "C" void kernel_launch(void* const* d_in, const int* in_sizes, int n_in,
                              void* d_out, int out_size)
{
    const float* sp = (const float*)d_in[0];   // spatial  [16,2048,64] f32
    const float* tp = (const float*)d_in[1];   // temporal [16, 168,64] f32
    float* out = (float*)d_out;                // [16,2216,2216] f32

    cudaFuncSetAttribute(stg_sym_kernel, cudaFuncAttributeMaxDynamicSharedMemorySize, SMEM_BYTES);
    dim3 grid(PAIRS, BB);
    stg_sym_kernel<<<grid, 256, SMEM_BYTES>>>(sp, tp, out);
}